// round 15
// baseline (speedup 1.0000x reference)
#include <cuda_runtime.h>
#include <cuda_bf16.h>
#include <math.h>
#include <stdint.h>

// Problem constants
#define M_TOK   65536          // B*nvars*H
#define C_DIM   256
#define N_QKV   768
#define D_FF    512
#define NUNITS  8192

// ---------------- scratch ----------------
// Packed hi/lo format: uint32 = bf16(hi) | bf16(lo)<<16, hi+lo ~= fp32 value (~19 bits)
__device__ float    g_qkv[(size_t)M_TOK * N_QKV];          // f32 (attention input)
__device__ uint32_t g_src_hl[(size_t)M_TOK * C_DIM];       // packed src
__device__ uint32_t g_ot_hl [(size_t)M_TOK * C_DIM];       // packed out_tok
__device__ uint32_t g_oh_hl [(size_t)M_TOK * C_DIM];       // packed out_hid
__device__ uint32_t g_h_hl  [2ull * M_TOK * D_FF];         // packed FF hidden
__device__ float    g_pre[(size_t)M_TOK * C_DIM];
__device__ float    g_psum[3 * 256 * 256];
__device__ float    g_psq [3 * 256 * 256];
__device__ float    g_S[3 * 256];
__device__ float    g_T[3 * 256];
__device__ uint32_t g_whl[720896];   // packed transposed weights [N][K]
__device__ float    g_b1c[2 * 512]; // BN-folded ff1 bias
#define WQ_O  0
#define W1A_O 196608
#define W1B_O 327680
#define W2A_O 458752
#define W2B_O 589824

// ---------------- helpers ----------------
__device__ __forceinline__ uint32_t packhl(float v) {
    __nv_bfloat16 h = __float2bfloat16(v);
    float hf = __bfloat162float(h);
    __nv_bfloat16 l = __float2bfloat16(v - hf);
    return (uint32_t)__bfloat16_as_ushort(h) | ((uint32_t)__bfloat16_as_ushort(l) << 16);
}
__device__ __forceinline__ float unpackf(uint32_t p) {
    return __bfloat162float(__ushort_as_bfloat16((unsigned short)(p & 0xFFFF)))
         + __bfloat162float(__ushort_as_bfloat16((unsigned short)(p >> 16)));
}
__device__ __forceinline__ void mma16(float* d, const uint32_t* a, const uint32_t* b) {
    asm volatile(
        "mma.sync.aligned.m16n8k16.row.col.f32.bf16.bf16.f32 "
        "{%0,%1,%2,%3},{%4,%5,%6,%7},{%8,%9},{%0,%1,%2,%3};"
        : "+f"(d[0]), "+f"(d[1]), "+f"(d[2]), "+f"(d[3])
        : "r"(a[0]), "r"(a[1]), "r"(a[2]), "r"(a[3]), "r"(b[0]), "r"(b[1]));
}
__device__ __forceinline__ void ldx4(uint32_t* r, uint32_t a) {
    asm volatile("ldmatrix.sync.aligned.m8n8.x4.shared.b16 {%0,%1,%2,%3}, [%4];"
        : "=r"(r[0]), "=r"(r[1]), "=r"(r[2]), "=r"(r[3]) : "r"(a));
}

// Peel packed hi/lo planes: 8 packed u32 -> uint4 of 8 hi-bf16 + uint4 of 8 lo-bf16
#define UNPACK8(p_, h4_, l4_) { \
    h4_.x = __byte_perm(p_[0], p_[1], 0x5410); l4_.x = __byte_perm(p_[0], p_[1], 0x7632); \
    h4_.y = __byte_perm(p_[2], p_[3], 0x5410); l4_.y = __byte_perm(p_[2], p_[3], 0x7632); \
    h4_.z = __byte_perm(p_[4], p_[5], 0x5410); l4_.z = __byte_perm(p_[4], p_[5], 0x7632); \
    h4_.w = __byte_perm(p_[6], p_[7], 0x5410); l4_.w = __byte_perm(p_[6], p_[7], 0x7632); }

// SMEM: [stage][AsH,AsL,BsH,BsL][4KB]; 16x16 bf16 tile = 4 contiguous 8x8 (512B),
// ldmatrix.x4 addr = tilebase + lane*16.  (layout verified in R7)
// 256 threads, 8 warps, warp-tile 64x32 (R10 config — best measured).
#define GEMM_PROLOG() \
    const int tid = threadIdx.x, lane = tid & 31, w = tid >> 5; \
    const int gid = lane >> 2, tig = lane & 3; \
    const int mt0 = (w >> 2) * 4, nt0 = (w & 3) * 2; \
    const int m_off = mt0 * 16, n_off = nt0 * 16; \
    const int cRow = blockIdx.y << 7, cCol = blockIdx.x << 7; \
    const int lr = tid >> 1, kh = tid & 1; \
    const int a_g = ((lr >> 4) << 5) + ((kh * 2 + ((lr & 15) >> 3)) << 3) + (lr & 7); \
    const uint32_t smb = (uint32_t)__cvta_generic_to_shared(sm); \
    uint32_t pa[8], pb[8]; \
    float acc[4][4][4]; \
    _Pragma("unroll") for (int i = 0; i < 4; i++) \
    _Pragma("unroll") for (int j = 0; j < 4; j++) \
    _Pragma("unroll") for (int r = 0; r < 4; r++) acc[i][j][r] = 0.f;

#define CVT_STORE(stg) { \
    uint4 h4_, l4_; \
    UNPACK8(pa, h4_, l4_); \
    ((uint4*)(&sm[stg][0][0]))[a_g] = h4_; \
    ((uint4*)(&sm[stg][1][0]))[a_g] = l4_; \
    UNPACK8(pb, h4_, l4_); \
    ((uint4*)(&sm[stg][2][0]))[a_g] = h4_; \
    ((uint4*)(&sm[stg][3][0]))[a_g] = l4_; }

// Three independent passes over the 16 accumulators: within a pass every mma
// targets a DIFFERENT accumulator -> no serial dependency chains at issue.
// Per-accumulator contribution order unchanged (hi*lo, lo*hi, hi*hi) -> bitwise
// identical results to the fused-order version.
#define COMPUTE_TILE(stg) { \
    const uint32_t bAH = smb + (stg) * 16384 + (uint32_t)lane * 16; \
    uint32_t aH[4][4], aL[4][4], bH[2][4], bL[2][4]; \
    _Pragma("unroll") for (int i = 0; i < 4; i++) { \
        ldx4(aH[i], bAH + (mt0 + i) * 512); \
        ldx4(aL[i], bAH + 4096 + (mt0 + i) * 512); } \
    _Pragma("unroll") for (int j2 = 0; j2 < 2; j2++) { \
        ldx4(bH[j2], bAH + 8192  + (nt0 + j2) * 512); \
        ldx4(bL[j2], bAH + 12288 + (nt0 + j2) * 512); } \
    _Pragma("unroll") for (int i = 0; i < 4; i++) \
    _Pragma("unroll") for (int j = 0; j < 4; j++) { \
        uint32_t bl_[2] = {bL[j >> 1][j & 1], bL[j >> 1][(j & 1) + 2]}; \
        mma16(acc[i][j], aH[i], bl_); } \
    _Pragma("unroll") for (int i = 0; i < 4; i++) \
    _Pragma("unroll") for (int j = 0; j < 4; j++) { \
        uint32_t bh_[2] = {bH[j >> 1][j & 1], bH[j >> 1][(j & 1) + 2]}; \
        mma16(acc[i][j], aL[i], bh_); } \
    _Pragma("unroll") for (int i = 0; i < 4; i++) \
    _Pragma("unroll") for (int j = 0; j < 4; j++) { \
        uint32_t bh_[2] = {bH[j >> 1][j & 1], bH[j >> 1][(j & 1) + 2]}; \
        mma16(acc[i][j], aH[i], bh_); } }

#define GEMM_LOOP(LOADM) \
    LOADM(0); CVT_STORE(0); \
    __syncthreads(); \
    { int p = 0; \
      for (int it = 0; it < NIT; it++) { \
        if (it + 1 < NIT) LOADM(it + 1); \
        COMPUTE_TILE(p); \
        if (it + 1 < NIT) CVT_STORE(p ^ 1); \
        __syncthreads(); \
        p ^= 1; } }

// Packed operand loaders (8 consecutive K elements per thread)
#define HL_LDA(base, ld, it) { \
    const uint32_t* p_ = (base) + (size_t)(cRow + lr) * (ld) + (it) * 16 + kh * 8; \
    uint4 q0 = *(const uint4*)p_; uint4 q1 = *(const uint4*)(p_ + 4); \
    pa[0]=q0.x; pa[1]=q0.y; pa[2]=q0.z; pa[3]=q0.w; \
    pa[4]=q1.x; pa[5]=q1.y; pa[6]=q1.z; pa[7]=q1.w; }
#define HL_LDB(base, ld, it) { \
    const uint32_t* p_ = (base) + (size_t)(cCol + lr) * (ld) + (it) * 16 + kh * 8; \
    uint4 q0 = *(const uint4*)p_; uint4 q1 = *(const uint4*)(p_ + 4); \
    pb[0]=q0.x; pb[1]=q0.y; pb[2]=q0.z; pb[3]=q0.w; \
    pb[4]=q1.x; pb[5]=q1.y; pb[6]=q1.z; pb[7]=q1.w; }

// ======================= pre-pass: split src to packed =======================
__global__ void __launch_bounds__(256) k_split_src(const float* __restrict__ src)
{
    const size_t i = (size_t)blockIdx.x * 256 + threadIdx.x;   // float4 index
    float4 v = ((const float4*)src)[i];
    uint4 o;
    o.x = packhl(v.x); o.y = packhl(v.y); o.z = packhl(v.z); o.w = packhl(v.w);
    ((uint4*)g_src_hl)[i] = o;
}

// ======================= weight prep: transpose + optional BN-scale + split =======================
// in [K][N] f32 -> g_whl+out_off [N][K] packed.  s_off>=0: scale row k by g_S[s_off+k].
__global__ void k_prep_w(const float* __restrict__ in, int out_off, int K, int N, int s_off)
{
    __shared__ float t[32][33];
    uint32_t* out = g_whl + out_off;
    const int bx = blockIdx.x * 32, by = blockIdx.y * 32;   // bx over N, by over K
    const int x = threadIdx.x, y = threadIdx.y;
#pragma unroll
    for (int dy = 0; dy < 32; dy += 8) {
        float v = in[(size_t)(by + y + dy) * N + bx + x];
        if (s_off >= 0) v *= g_S[s_off + by + y + dy];
        t[y + dy][x] = v;
    }
    __syncthreads();
#pragma unroll
    for (int dy = 0; dy < 32; dy += 8)
        out[(size_t)(bx + y + dy) * K + by + x] = packhl(t[x][y + dy]);
}

// ======================= BN-folded ff1 bias: b1'[n] = b1[n] + sum_k T[k]*W1[k][n] =======================
__global__ void k_bias1(const float* __restrict__ w1a, const float* __restrict__ b1a,
                        const float* __restrict__ w1b, const float* __restrict__ b1b)
{
    const int z = blockIdx.x, n = threadIdx.x;   // 2 x 512
    const float* W = z ? w1b : w1a;
    const float* b = z ? b1b : b1a;
    const float* T = g_T + z * 256;
    float s = b[n];
    for (int k = 0; k < 256; k++) s += T[k] * W[(size_t)k * 512 + n];
    g_b1c[z * 512 + n] = s;
}

// ======================= GEMM 1: qkv = src @ w_qkv + b_qkv =======================
__global__ void __launch_bounds__(256) k_qkv_tc(const float* __restrict__ bias)
{
    constexpr int NIT = 16;
    __shared__ __align__(16) uint32_t sm[2][4][1024];
    GEMM_PROLOG();
    const uint32_t* WB = g_whl + WQ_O;
#define QKV_LD(it) { HL_LDA(g_src_hl, 256, it); HL_LDB(WB, 256, it); }
    GEMM_LOOP(QKV_LD);
#pragma unroll
    for (int i = 0; i < 4; i++)
#pragma unroll
        for (int j = 0; j < 4; j++) {
            int row0 = cRow + m_off + i * 16 + gid;
            int col  = cCol + n_off + j * 8 + tig * 2;
            float b0 = bias[col], b1 = bias[col + 1];
            float2 v0 = {acc[i][j][0] + b0, acc[i][j][1] + b1};
            float2 v1 = {acc[i][j][2] + b0, acc[i][j][3] + b1};
            *(float2*)&g_qkv[(size_t)row0 * N_QKV + col] = v0;
            *(float2*)&g_qkv[(size_t)(row0 + 8) * N_QKV + col] = v1;
        }
}

// ======================= GEMM 2: h = gelu(o @ W1' + b1') (BN folded into W1',b1') =======================
__global__ void __launch_bounds__(256) k_ff1_tc()
{
    constexpr int NIT = 16;
    __shared__ __align__(16) uint32_t sm[2][4][1024];
    GEMM_PROLOG();
    const int bz = blockIdx.z;
    const uint32_t* Ahl = bz ? g_oh_hl : g_ot_hl;
    const uint32_t* WB  = g_whl + (bz ? W1B_O : W1A_O);
    const float* bias   = g_b1c + bz * 512;
    uint32_t* Cout = g_h_hl + (size_t)bz * ((size_t)M_TOK * D_FF);
#define FF1_LD(it) { HL_LDA(Ahl, 256, it); HL_LDB(WB, 256, it); }
    GEMM_LOOP(FF1_LD);
#pragma unroll
    for (int i = 0; i < 4; i++)
#pragma unroll
        for (int j = 0; j < 4; j++) {
            int row0 = cRow + m_off + i * 16 + gid;
            int col  = cCol + n_off + j * 8 + tig * 2;
            float b0 = bias[col], b1 = bias[col + 1];
            float x0 = acc[i][j][0] + b0, x1 = acc[i][j][1] + b1;
            float x2 = acc[i][j][2] + b0, x3 = acc[i][j][3] + b1;
            float g0 = 0.5f * x0 * (1.f + erff(x0 * 0.70710678118654752f));
            float g1 = 0.5f * x1 * (1.f + erff(x1 * 0.70710678118654752f));
            float g2v = 0.5f * x2 * (1.f + erff(x2 * 0.70710678118654752f));
            float g3 = 0.5f * x3 * (1.f + erff(x3 * 0.70710678118654752f));
            uint2 u0 = {packhl(g0), packhl(g1)};
            uint2 u1 = {packhl(g2v), packhl(g3)};
            *(uint2*)&Cout[(size_t)row0 * D_FF + col] = u0;
            *(uint2*)&Cout[(size_t)(row0 + 8) * D_FF + col] = u1;
        }
}

// ======================= GEMM 3: pre = src + h1@W2a + h2@W2b + biases =======================
__global__ void __launch_bounds__(256) k_g2_tc(
    const float* __restrict__ b2a, const float* __restrict__ b2b,
    const float* __restrict__ src)
{
    constexpr int NIT = 64;   // 2 branches x 512/16
    __shared__ __align__(16) uint32_t sm[2][4][1024];
    GEMM_PROLOG();
#define G2_LD(it) { \
    const int pp_ = (it) >> 5, k0it_ = (it) & 31; \
    const uint32_t* Ahl_ = g_h_hl + (size_t)pp_ * ((size_t)M_TOK * D_FF); \
    const uint32_t* WB_  = g_whl + (pp_ ? W2B_O : W2A_O); \
    HL_LDA(Ahl_, 512, k0it_); HL_LDB(WB_, 512, k0it_); }
    GEMM_LOOP(G2_LD);
#pragma unroll
    for (int i = 0; i < 4; i++)
#pragma unroll
        for (int j = 0; j < 4; j++) {
            int row0 = cRow + m_off + i * 16 + gid;
            int col  = cCol + n_off + j * 8 + tig * 2;
            float b0 = b2a[col] + b2b[col], b1 = b2a[col + 1] + b2b[col + 1];
            float2 s0 = *(const float2*)&src[(size_t)row0 * C_DIM + col];
            float2 s1 = *(const float2*)&src[(size_t)(row0 + 8) * C_DIM + col];
            float2 v0 = {acc[i][j][0] + b0 + s0.x, acc[i][j][1] + b1 + s0.y};
            float2 v1 = {acc[i][j][2] + b0 + s1.x, acc[i][j][3] + b1 + s1.y};
            *(float2*)&g_pre[(size_t)row0 * C_DIM + col] = v0;
            *(float2*)&g_pre[(size_t)(row0 + 8) * C_DIM + col] = v1;
        }
}

// ======================= Attention: one block per (b,n,head) unit =======================
__global__ void __launch_bounds__(128) k_attn(
    const float* __restrict__ E,
    const float* __restrict__ w_dpk, const float* __restrict__ b_dpk,
    const float* __restrict__ w_dpv, const float* __restrict__ b_dpv)
{
    __shared__ float sQ[64][33], sK[64][33], sV[64][33];
    __shared__ float sP[64][16];
    __shared__ float sKdp[16][32], sVdp[16][32];
    __shared__ float sEQ[64][33];
    __shared__ float sEK[16][32];
    __shared__ float sH[32][33];

    const int u    = blockIdx.x;
    const int head = u & 7;
    const int bn   = u >> 3;
    const int tid  = threadIdx.x;

    const float* base = g_qkv + (size_t)bn * (64 * N_QKV) + head * 32;
    for (int i = tid; i < 2048; i += 128) {
        int e = i >> 5, d = i & 31;
        const float* p = base + e * N_QKV + d;
        sQ[e][d] = p[0];
        sK[e][d] = p[256];
        sV[e][d] = p[512];
    }
    __syncthreads();

    if (tid < 64) {
        float l[16];
#pragma unroll
        for (int c = 0; c < 16; c++) l[c] = __ldg(&b_dpk[c]);
#pragma unroll 8
        for (int d = 0; d < 32; d++) {
            float kv = sK[tid][d];
#pragma unroll
            for (int c = 0; c < 16; c++) l[c] += kv * __ldg(&w_dpk[d * 16 + c]);
        }
        float m = l[0];
#pragma unroll
        for (int c = 1; c < 16; c++) m = fmaxf(m, l[c]);
        float s = 0.f;
#pragma unroll
        for (int c = 0; c < 16; c++) { l[c] = expf(l[c] - m); s += l[c]; }
        float inv = 1.f / s;
#pragma unroll
        for (int c = 0; c < 16; c++) sP[tid][c] = l[c] * inv;
    }
    __syncthreads();

#pragma unroll
    for (int r = 0; r < 4; r++) {
        int i = tid + (r << 7);
        int c = i >> 5, d = i & 31;
        float acc = 0.f;
#pragma unroll 8
        for (int e = 0; e < 64; e++) acc += sP[e][c] * sK[e][d];
        sKdp[c][d] = acc;
    }
#pragma unroll
    for (int r = 0; r < 16; r++) {
        int i = tid + (r << 7);
        int g = i >> 5, d = i & 31;
        float acc = 0.f;
        for (int a = 0; a <= g; a++) acc += __ldg(&E[g * 64 + a]) * sQ[a][d];
        sEQ[g][d] = acc;
    }
    __syncthreads();

    if (tid < 64) {
        float l[16];
#pragma unroll
        for (int c = 0; c < 16; c++) l[c] = __ldg(&b_dpv[c]);
#pragma unroll 8
        for (int d = 0; d < 32; d++) {
            float vv = sV[tid][d];
#pragma unroll
            for (int c = 0; c < 16; c++) l[c] += vv * __ldg(&w_dpv[d * 16 + c]);
        }
        float m = l[0];
#pragma unroll
        for (int c = 1; c < 16; c++) m = fmaxf(m, l[c]);
        float s = 0.f;
#pragma unroll
        for (int c = 0; c < 16; c++) { l[c] = expf(l[c] - m); s += l[c]; }
        float inv = 1.f / s;
#pragma unroll
        for (int c = 0; c < 16; c++) sP[tid][c] = l[c] * inv;
    }
    __syncthreads();

#pragma unroll
    for (int r = 0; r < 4; r++) {
        int i = tid + (r << 7);
        int c = i >> 5, d = i & 31;
        float acc = 0.f;
#pragma unroll 8
        for (int e = 0; e < 64; e++) acc += sP[e][c] * sV[e][d];
        sVdp[c][d] = acc;
    }
#pragma unroll
    for (int r = 0; r < 4; r++) {
        int i = tid + (r << 7);
        int g = i >> 5, d = i & 31;
        float acc = 0.f;
        for (int a = 0; a <= g; a++) acc += __ldg(&E[g * 64 + a]) * sKdp[a][d];
        sEK[g][d] = acc;
    }
    __syncthreads();

    if (tid < 64) {
        const int e = tid;
        float st[16];
#pragma unroll
        for (int c = 0; c < 16; c++) {
            float acc = 0.f;
#pragma unroll
            for (int d = 0; d < 32; d++) acc += sEQ[e][d] * sEK[c][d];
            st[c] = acc * 5.656854249492381f;
        }
        float m = st[0];
#pragma unroll
        for (int c = 1; c < 16; c++) m = fmaxf(m, st[c]);
        float s = 0.f;
#pragma unroll
        for (int c = 0; c < 16; c++) { st[c] = expf(st[c] - m); s += st[c]; }
        float inv = 1.f / s;
#pragma unroll
        for (int c = 0; c < 16; c++) st[c] *= inv;
#pragma unroll
        for (int d = 0; d < 32; d++) {
            float acc = 0.f;
#pragma unroll
            for (int c = 0; c < 16; c++) acc += st[c] * sVdp[c][d];
            sEQ[e][d] = acc;
        }
    } else {
        const int idx = tid - 64;
        const int e = idx >> 1, h = idx & 1;
        float sh[16];
#pragma unroll
        for (int j = 0; j < 16; j++) {
            const int f = (h << 4) + j;
            float acc = 0.f;
#pragma unroll 8
            for (int a = 0; a < 64; a++) acc += sQ[a][e] * sK[a][f];
            sh[j] = acc * 8.0f;
        }
        float m = sh[0];
#pragma unroll
        for (int j = 1; j < 16; j++) m = fmaxf(m, sh[j]);
        m = fmaxf(m, __shfl_xor_sync(0xffffffffu, m, 1));
        float s = 0.f;
#pragma unroll
        for (int j = 0; j < 16; j++) { sh[j] = expf(sh[j] - m); s += sh[j]; }
        s += __shfl_xor_sync(0xffffffffu, s, 1);
        float inv = 1.f / s;
#pragma unroll
        for (int j = 0; j < 16; j++) sH[e][(h << 4) + j] = sh[j] * inv;
    }
    __syncthreads();

    uint32_t* otp = g_ot_hl + (size_t)u * 2048;
    uint32_t* ohp = g_oh_hl + (size_t)u * 2048;
#pragma unroll
    for (int r = 0; r < 16; r++) {
        int i = tid + (r << 7);
        int a = i >> 5, e = i & 31;
        otp[i] = packhl(sEQ[a][e]);
        float acc = 0.f;
#pragma unroll
        for (int f = 0; f < 32; f++) acc += sH[e][f] * sV[a][f];
        ohp[i] = packhl(acc);
    }
}

// ======================= BN statistics (deterministic two-stage) =======================
__global__ void __launch_bounds__(256) k_bn_partial(int slot)
{
    const int c = threadIdx.x;
    const size_t base = (size_t)blockIdx.x * 65536;
    float s = 0.f, q = 0.f;
    if (slot == 2) {
        for (int r = 0; r < 256; r++) {
            float v = g_pre[base + (size_t)(r << 8) + c];
            s += v; q += v * v;
        }
    } else {
        const uint32_t* x = slot ? g_oh_hl : g_ot_hl;
        for (int r = 0; r < 256; r++) {
            float v = unpackf(x[base + (size_t)(r << 8) + c]);
            s += v; q += v * v;
        }
    }
    g_psum[slot * 65536 + (blockIdx.x << 8) + c] = s;
    g_psq [slot * 65536 + (blockIdx.x << 8) + c] = q;
}

__global__ void __launch_bounds__(256) k_bn_finalize(
    int slot, const float* __restrict__ g, const float* __restrict__ b)
{
    const int c = threadIdx.x;
    const float* ps = g_psum + slot * 65536;
    const float* pq = g_psq  + slot * 65536;
    float s = 0.f, q = 0.f;
    for (int i = 0; i < 256; i++) { s += ps[(i << 8) + c]; q += pq[(i << 8) + c]; }
    const float inv = 1.f / 65536.f;
    float mean = s * inv;
    float var  = q * inv - mean * mean;
    float rstd = rsqrtf(var + 1e-5f);
    float sc = g[c] * rstd;
    g_S[slot * 256 + c] = sc;
    g_T[slot * 256 + c] = b[c] - mean * sc;
}

// ======================= Final BN apply =======================
__global__ void __launch_bounds__(256) k_bn_apply(float* __restrict__ out)
{
    const size_t i = (size_t)blockIdx.x * 256 + threadIdx.x;
    float4 v = ((const float4*)g_pre)[i];
    const int c = (int)((i & 63) << 2);
    const float* S = g_S + 512;
    const float* T = g_T + 512;
    v.x = v.x * S[c + 0] + T[c + 0];
    v.y = v.y * S[c + 1] + T[c + 1];
    v.z = v.z * S[c + 2] + T[c + 2];
    v.w = v.w * S[c + 3] + T[c + 3];
    ((float4*)out)[i] = v;
}

// ======================= launch =======================
extern "C" void kernel_launch(void* const* d_in, const int* in_sizes, int n_in,
                              void* d_out, int out_size)
{
    const float* src    = (const float*)d_in[0];
    const float* ema    = (const float*)d_in[1];
    const float* w_qkv  = (const float*)d_in[2];
    const float* b_qkv  = (const float*)d_in[3];
    const float* w_dpk  = (const float*)d_in[4];
    const float* b_dpk  = (const float*)d_in[5];
    const float* w_dpv  = (const float*)d_in[6];
    const float* b_dpv  = (const float*)d_in[7];
    const float* bn1_g  = (const float*)d_in[8];
    const float* bn1_b  = (const float*)d_in[9];
    const float* bn2_g  = (const float*)d_in[10];
    const float* bn2_b  = (const float*)d_in[11];
    const float* bna_g  = (const float*)d_in[12];
    const float* bna_b  = (const float*)d_in[13];
    const float* ff1_w1 = (const float*)d_in[14];
    const float* ff1_b1 = (const float*)d_in[15];
    const float* ff1_w2 = (const float*)d_in[16];
    const float* ff1_b2 = (const float*)d_in[17];
    const float* ff2_w1 = (const float*)d_in[18];
    const float* ff2_b1 = (const float*)d_in[19];
    const float* ff2_w2 = (const float*)d_in[20];
    const float* ff2_b2 = (const float*)d_in[21];
    float* out = (float*)d_out;

    // pre-split operands that don't depend on BN stats
    k_split_src<<<16384, 256>>>(src);
    k_prep_w<<<dim3(24,  8), dim3(32, 8)>>>(w_qkv,  WQ_O,  256, 768, -1);
    k_prep_w<<<dim3( 8, 16), dim3(32, 8)>>>(ff1_w2, W2A_O, 512, 256, -1);
    k_prep_w<<<dim3( 8, 16), dim3(32, 8)>>>(ff2_w2, W2B_O, 512, 256, -1);

    k_qkv_tc<<<dim3(N_QKV / 128, M_TOK / 128), 256>>>(b_qkv);
    k_attn<<<NUNITS, 128>>>(ema, w_dpk, b_dpk, w_dpv, b_dpv);
    k_bn_partial<<<256, 256>>>(0);
    k_bn_partial<<<256, 256>>>(1);
    k_bn_finalize<<<1, 256>>>(0, bn1_g, bn1_b);
    k_bn_finalize<<<1, 256>>>(1, bn2_g, bn2_b);

    // BN-folded ff1 weights + bias (need g_S/g_T from finalize)
    k_prep_w<<<dim3(16,  8), dim3(32, 8)>>>(ff1_w1, W1A_O, 256, 512, 0);
    k_prep_w<<<dim3(16,  8), dim3(32, 8)>>>(ff2_w1, W1B_O, 256, 512, 256);
    k_bias1<<<2, 512>>>(ff1_w1, ff1_b1, ff2_w1, ff2_b1);

    k_ff1_tc<<<dim3(D_FF / 128, M_TOK / 128, 2), 256>>>();
    k_g2_tc<<<dim3(C_DIM / 128, M_TOK / 128), 256>>>(ff1_b2, ff2_b2, src);
    k_bn_partial<<<256, 256>>>(2);
    k_bn_finalize<<<1, 256>>>(2, bna_g, bna_b);
    k_bn_apply<<<(M_TOK * C_DIM / 4) / 256, 256>>>(out);
}

// round 17
// speedup vs baseline: 1.2067x; 1.2067x over previous
#include <cuda_runtime.h>
#include <cuda_bf16.h>
#include <math.h>
#include <stdint.h>

// Problem constants
#define M_TOK   65536          // B*nvars*H
#define C_DIM   256
#define N_QKV   768
#define D_FF    512
#define NUNITS  8192

// ---------------- scratch ----------------
// Packed hi/lo format: uint32 = bf16(hi) | bf16(lo)<<16, hi+lo ~= fp32 value (~19 bits)
__device__ float    g_qkv[(size_t)M_TOK * N_QKV];          // f32 (attention input)
__device__ uint32_t g_src_hl[(size_t)M_TOK * C_DIM];       // packed src
__device__ uint32_t g_ot_hl [(size_t)M_TOK * C_DIM];       // packed out_tok
__device__ uint32_t g_oh_hl [(size_t)M_TOK * C_DIM];       // packed out_hid
__device__ uint32_t g_h_hl  [2ull * M_TOK * D_FF];         // packed FF hidden
__device__ float    g_pre[(size_t)M_TOK * C_DIM];
__device__ float    g_psum[3 * 256 * 256];
__device__ float    g_psq [3 * 256 * 256];
__device__ float    g_S[3 * 256];
__device__ float    g_T[3 * 256];
__device__ uint32_t g_whl[720896];   // packed transposed weights [N][K]
__device__ float    g_b1c[2 * 512]; // BN-folded ff1 bias
#define WQ_O  0
#define W1A_O 196608
#define W1B_O 327680
#define W2A_O 458752
#define W2B_O 589824

// ---------------- helpers ----------------
__device__ __forceinline__ uint32_t packhl(float v) {
    __nv_bfloat16 h = __float2bfloat16(v);
    float hf = __bfloat162float(h);
    __nv_bfloat16 l = __float2bfloat16(v - hf);
    return (uint32_t)__bfloat16_as_ushort(h) | ((uint32_t)__bfloat16_as_ushort(l) << 16);
}
__device__ __forceinline__ float unpackf(uint32_t p) {
    return __bfloat162float(__ushort_as_bfloat16((unsigned short)(p & 0xFFFF)))
         + __bfloat162float(__ushort_as_bfloat16((unsigned short)(p >> 16)));
}
__device__ __forceinline__ void mma16(float* d, const uint32_t* a, const uint32_t* b) {
    asm volatile(
        "mma.sync.aligned.m16n8k16.row.col.f32.bf16.bf16.f32 "
        "{%0,%1,%2,%3},{%4,%5,%6,%7},{%8,%9},{%0,%1,%2,%3};"
        : "+f"(d[0]), "+f"(d[1]), "+f"(d[2]), "+f"(d[3])
        : "r"(a[0]), "r"(a[1]), "r"(a[2]), "r"(a[3]), "r"(b[0]), "r"(b[1]));
}
__device__ __forceinline__ void ldx4(uint32_t* r, uint32_t a) {
    asm volatile("ldmatrix.sync.aligned.m8n8.x4.shared.b16 {%0,%1,%2,%3}, [%4];"
        : "=r"(r[0]), "=r"(r[1]), "=r"(r[2]), "=r"(r[3]) : "r"(a));
}

// Peel packed hi/lo planes: 8 packed u32 -> uint4 of 8 hi-bf16 + uint4 of 8 lo-bf16
#define UNPACK8(p_, h4_, l4_) { \
    h4_.x = __byte_perm(p_[0], p_[1], 0x5410); l4_.x = __byte_perm(p_[0], p_[1], 0x7632); \
    h4_.y = __byte_perm(p_[2], p_[3], 0x5410); l4_.y = __byte_perm(p_[2], p_[3], 0x7632); \
    h4_.z = __byte_perm(p_[4], p_[5], 0x5410); l4_.z = __byte_perm(p_[4], p_[5], 0x7632); \
    h4_.w = __byte_perm(p_[6], p_[7], 0x5410); l4_.w = __byte_perm(p_[6], p_[7], 0x7632); }

// SMEM: [stage][AsH,AsL,BsH,BsL][4KB]; 16x16 bf16 tile = 4 contiguous 8x8 (512B),
// ldmatrix.x4 addr = tilebase + lane*16.  (layout verified in R7)
// 256 threads, 8 warps, warp-tile 64x32 (R10 config — best measured).
#define GEMM_PROLOG() \
    const int tid = threadIdx.x, lane = tid & 31, w = tid >> 5; \
    const int gid = lane >> 2, tig = lane & 3; \
    const int mt0 = (w >> 2) * 4, nt0 = (w & 3) * 2; \
    const int m_off = mt0 * 16, n_off = nt0 * 16; \
    const int cRow = blockIdx.y << 7, cCol = blockIdx.x << 7; \
    const int lr = tid >> 1, kh = tid & 1; \
    const int a_g = ((lr >> 4) << 5) + ((kh * 2 + ((lr & 15) >> 3)) << 3) + (lr & 7); \
    const uint32_t smb = (uint32_t)__cvta_generic_to_shared(sm); \
    uint32_t pa[8], pb[8]; \
    float acc[4][4][4]; \
    _Pragma("unroll") for (int i = 0; i < 4; i++) \
    _Pragma("unroll") for (int j = 0; j < 4; j++) \
    _Pragma("unroll") for (int r = 0; r < 4; r++) acc[i][j][r] = 0.f;

#define CVT_STORE(stg) { \
    uint4 h4_, l4_; \
    UNPACK8(pa, h4_, l4_); \
    ((uint4*)(&sm[stg][0][0]))[a_g] = h4_; \
    ((uint4*)(&sm[stg][1][0]))[a_g] = l4_; \
    UNPACK8(pb, h4_, l4_); \
    ((uint4*)(&sm[stg][2][0]))[a_g] = h4_; \
    ((uint4*)(&sm[stg][3][0]))[a_g] = l4_; }

// R10 fused order (best measured): 3 mmas grouped per accumulator.
#define COMPUTE_TILE(stg) { \
    const uint32_t bAH = smb + (stg) * 16384 + (uint32_t)lane * 16; \
    uint32_t aH[4][4], aL[4][4], bH[2][4], bL[2][4]; \
    _Pragma("unroll") for (int i = 0; i < 4; i++) { \
        ldx4(aH[i], bAH + (mt0 + i) * 512); \
        ldx4(aL[i], bAH + 4096 + (mt0 + i) * 512); } \
    _Pragma("unroll") for (int j2 = 0; j2 < 2; j2++) { \
        ldx4(bH[j2], bAH + 8192  + (nt0 + j2) * 512); \
        ldx4(bL[j2], bAH + 12288 + (nt0 + j2) * 512); } \
    _Pragma("unroll") for (int i = 0; i < 4; i++) \
    _Pragma("unroll") for (int j = 0; j < 4; j++) { \
        const int j2_ = j >> 1, g_ = j & 1; \
        uint32_t bh_[2] = {bH[j2_][g_], bH[j2_][g_ + 2]}; \
        uint32_t bl_[2] = {bL[j2_][g_], bL[j2_][g_ + 2]}; \
        mma16(acc[i][j], aH[i], bl_); \
        mma16(acc[i][j], aL[i], bh_); \
        mma16(acc[i][j], aH[i], bh_); } }

#define GEMM_LOOP(LOADM) \
    LOADM(0); CVT_STORE(0); \
    __syncthreads(); \
    { int p = 0; \
      for (int it = 0; it < NIT; it++) { \
        if (it + 1 < NIT) LOADM(it + 1); \
        COMPUTE_TILE(p); \
        if (it + 1 < NIT) CVT_STORE(p ^ 1); \
        __syncthreads(); \
        p ^= 1; } }

// Packed operand loaders (8 consecutive K elements per thread)
#define HL_LDA(base, ld, it) { \
    const uint32_t* p_ = (base) + (size_t)(cRow + lr) * (ld) + (it) * 16 + kh * 8; \
    uint4 q0 = *(const uint4*)p_; uint4 q1 = *(const uint4*)(p_ + 4); \
    pa[0]=q0.x; pa[1]=q0.y; pa[2]=q0.z; pa[3]=q0.w; \
    pa[4]=q1.x; pa[5]=q1.y; pa[6]=q1.z; pa[7]=q1.w; }
#define HL_LDB(base, ld, it) { \
    const uint32_t* p_ = (base) + (size_t)(cCol + lr) * (ld) + (it) * 16 + kh * 8; \
    uint4 q0 = *(const uint4*)p_; uint4 q1 = *(const uint4*)(p_ + 4); \
    pb[0]=q0.x; pb[1]=q0.y; pb[2]=q0.z; pb[3]=q0.w; \
    pb[4]=q1.x; pb[5]=q1.y; pb[6]=q1.z; pb[7]=q1.w; }

// ======================= pre-pass: split src to packed =======================
__global__ void __launch_bounds__(256) k_split_src(const float* __restrict__ src)
{
    const size_t i = (size_t)blockIdx.x * 256 + threadIdx.x;   // float4 index
    float4 v = ((const float4*)src)[i];
    uint4 o;
    o.x = packhl(v.x); o.y = packhl(v.y); o.z = packhl(v.z); o.w = packhl(v.w);
    ((uint4*)g_src_hl)[i] = o;
}

// ======================= weight prep: transpose + optional BN-scale + split =======================
__global__ void k_prep_w(const float* __restrict__ in, int out_off, int K, int N, int s_off)
{
    __shared__ float t[32][33];
    uint32_t* out = g_whl + out_off;
    const int bx = blockIdx.x * 32, by = blockIdx.y * 32;   // bx over N, by over K
    const int x = threadIdx.x, y = threadIdx.y;
#pragma unroll
    for (int dy = 0; dy < 32; dy += 8) {
        float v = in[(size_t)(by + y + dy) * N + bx + x];
        if (s_off >= 0) v *= g_S[s_off + by + y + dy];
        t[y + dy][x] = v;
    }
    __syncthreads();
#pragma unroll
    for (int dy = 0; dy < 32; dy += 8)
        out[(size_t)(bx + y + dy) * K + by + x] = packhl(t[x][y + dy]);
}

// ======================= BN-folded ff1 bias =======================
__global__ void k_bias1(const float* __restrict__ w1a, const float* __restrict__ b1a,
                        const float* __restrict__ w1b, const float* __restrict__ b1b)
{
    const int z = blockIdx.x, n = threadIdx.x;   // 2 x 512
    const float* W = z ? w1b : w1a;
    const float* b = z ? b1b : b1a;
    const float* T = g_T + z * 256;
    float s = b[n];
    for (int k = 0; k < 256; k++) s += T[k] * W[(size_t)k * 512 + n];
    g_b1c[z * 512 + n] = s;
}

// ======================= GEMM 1: qkv = src @ w_qkv + b_qkv =======================
__global__ void __launch_bounds__(256) k_qkv_tc(const float* __restrict__ bias)
{
    constexpr int NIT = 16;
    __shared__ __align__(16) uint32_t sm[2][4][1024];
    GEMM_PROLOG();
    const uint32_t* WB = g_whl + WQ_O;
#define QKV_LD(it) { HL_LDA(g_src_hl, 256, it); HL_LDB(WB, 256, it); }
    GEMM_LOOP(QKV_LD);
#pragma unroll
    for (int i = 0; i < 4; i++)
#pragma unroll
        for (int j = 0; j < 4; j++) {
            int row0 = cRow + m_off + i * 16 + gid;
            int col  = cCol + n_off + j * 8 + tig * 2;
            float b0 = bias[col], b1 = bias[col + 1];
            float2 v0 = {acc[i][j][0] + b0, acc[i][j][1] + b1};
            float2 v1 = {acc[i][j][2] + b0, acc[i][j][3] + b1};
            *(float2*)&g_qkv[(size_t)row0 * N_QKV + col] = v0;
            *(float2*)&g_qkv[(size_t)(row0 + 8) * N_QKV + col] = v1;
        }
}

// ======================= GEMM 2: h = gelu(o @ W1' + b1') =======================
__global__ void __launch_bounds__(256) k_ff1_tc()
{
    constexpr int NIT = 16;
    __shared__ __align__(16) uint32_t sm[2][4][1024];
    GEMM_PROLOG();
    const int bz = blockIdx.z;
    const uint32_t* Ahl = bz ? g_oh_hl : g_ot_hl;
    const uint32_t* WB  = g_whl + (bz ? W1B_O : W1A_O);
    const float* bias   = g_b1c + bz * 512;
    uint32_t* Cout = g_h_hl + (size_t)bz * ((size_t)M_TOK * D_FF);
#define FF1_LD(it) { HL_LDA(Ahl, 256, it); HL_LDB(WB, 256, it); }
    GEMM_LOOP(FF1_LD);
#pragma unroll
    for (int i = 0; i < 4; i++)
#pragma unroll
        for (int j = 0; j < 4; j++) {
            int row0 = cRow + m_off + i * 16 + gid;
            int col  = cCol + n_off + j * 8 + tig * 2;
            float b0 = bias[col], b1 = bias[col + 1];
            float x0 = acc[i][j][0] + b0, x1 = acc[i][j][1] + b1;
            float x2 = acc[i][j][2] + b0, x3 = acc[i][j][3] + b1;
            float g0 = 0.5f * x0 * (1.f + erff(x0 * 0.70710678118654752f));
            float g1 = 0.5f * x1 * (1.f + erff(x1 * 0.70710678118654752f));
            float g2v = 0.5f * x2 * (1.f + erff(x2 * 0.70710678118654752f));
            float g3 = 0.5f * x3 * (1.f + erff(x3 * 0.70710678118654752f));
            uint2 u0 = {packhl(g0), packhl(g1)};
            uint2 u1 = {packhl(g2v), packhl(g3)};
            *(uint2*)&Cout[(size_t)row0 * D_FF + col] = u0;
            *(uint2*)&Cout[(size_t)(row0 + 8) * D_FF + col] = u1;
        }
}

// ======================= GEMM 3: pre = src + h1@W2a + h2@W2b + biases =======================
__global__ void __launch_bounds__(256) k_g2_tc(
    const float* __restrict__ b2a, const float* __restrict__ b2b,
    const float* __restrict__ src)
{
    constexpr int NIT = 64;
    __shared__ __align__(16) uint32_t sm[2][4][1024];
    GEMM_PROLOG();
#define G2_LD(it) { \
    const int pp_ = (it) >> 5, k0it_ = (it) & 31; \
    const uint32_t* Ahl_ = g_h_hl + (size_t)pp_ * ((size_t)M_TOK * D_FF); \
    const uint32_t* WB_  = g_whl + (pp_ ? W2B_O : W2A_O); \
    HL_LDA(Ahl_, 512, k0it_); HL_LDB(WB_, 512, k0it_); }
    GEMM_LOOP(G2_LD);
#pragma unroll
    for (int i = 0; i < 4; i++)
#pragma unroll
        for (int j = 0; j < 4; j++) {
            int row0 = cRow + m_off + i * 16 + gid;
            int col  = cCol + n_off + j * 8 + tig * 2;
            float b0 = b2a[col] + b2b[col], b1 = b2a[col + 1] + b2b[col + 1];
            float2 s0 = *(const float2*)&src[(size_t)row0 * C_DIM + col];
            float2 s1 = *(const float2*)&src[(size_t)(row0 + 8) * C_DIM + col];
            float2 v0 = {acc[i][j][0] + b0 + s0.x, acc[i][j][1] + b1 + s0.y};
            float2 v1 = {acc[i][j][2] + b0 + s1.x, acc[i][j][3] + b1 + s1.y};
            *(float2*)&g_pre[(size_t)row0 * C_DIM + col] = v0;
            *(float2*)&g_pre[(size_t)(row0 + 8) * C_DIM + col] = v1;
        }
}

// ======================= Attention: one block per (b,n,head) unit =======================
// EMA via first-order recurrence (exact structure of _build_ema_matrix):
//   EMA(x)[0] = x[0];  EMA(x)[g] = om*EMA(x)[g-1] + al*x[g],  om=E[64], al=E[65].
__global__ void __launch_bounds__(128) k_attn(
    const float* __restrict__ E,
    const float* __restrict__ w_dpk, const float* __restrict__ b_dpk,
    const float* __restrict__ w_dpv, const float* __restrict__ b_dpv)
{
    __shared__ float sQ[64][33], sK[64][33], sV[64][33];
    __shared__ float sP[64][16];
    __shared__ float sKdp[16][32], sVdp[16][32];
    __shared__ float sEQ[64][33];
    __shared__ float sEK[16][32];
    __shared__ float sH[32][33];

    const int u    = blockIdx.x;
    const int head = u & 7;
    const int bn   = u >> 3;
    const int tid  = threadIdx.x;
    const float om = __ldg(&E[64]);   // (1-alpha) = m[1][0]
    const float al = __ldg(&E[65]);   // alpha     = m[1][1]

    const float* base = g_qkv + (size_t)bn * (64 * N_QKV) + head * 32;
    for (int i = tid; i < 2048; i += 128) {
        int e = i >> 5, d = i & 31;
        const float* p = base + e * N_QKV + d;
        sQ[e][d] = p[0];
        sK[e][d] = p[256];
        sV[e][d] = p[512];
    }
    __syncthreads();

    if (tid < 64) {
        float l[16];
#pragma unroll
        for (int c = 0; c < 16; c++) l[c] = __ldg(&b_dpk[c]);
#pragma unroll 8
        for (int d = 0; d < 32; d++) {
            float kv = sK[tid][d];
#pragma unroll
            for (int c = 0; c < 16; c++) l[c] += kv * __ldg(&w_dpk[d * 16 + c]);
        }
        float m = l[0];
#pragma unroll
        for (int c = 1; c < 16; c++) m = fmaxf(m, l[c]);
        float s = 0.f;
#pragma unroll
        for (int c = 0; c < 16; c++) { l[c] = expf(l[c] - m); s += l[c]; }
        float inv = 1.f / s;
#pragma unroll
        for (int c = 0; c < 16; c++) sP[tid][c] = l[c] * inv;
    }
    __syncthreads();

    // phase 3: k_dp (all threads) + EMA(q) scan (threads 0-31)
#pragma unroll
    for (int r = 0; r < 4; r++) {
        int i = tid + (r << 7);
        int c = i >> 5, d = i & 31;
        float acc = 0.f;
#pragma unroll 8
        for (int e = 0; e < 64; e++) acc += sP[e][c] * sK[e][d];
        sKdp[c][d] = acc;
    }
    if (tid < 32) {
        const int d = tid;
        float v = sQ[0][d];
        sEQ[0][d] = v;
#pragma unroll 8
        for (int g = 1; g < 64; g++) {
            v = om * v + al * sQ[g][d];
            sEQ[g][d] = v;
        }
    }
    __syncthreads();

    if (tid < 64) {
        float l[16];
#pragma unroll
        for (int c = 0; c < 16; c++) l[c] = __ldg(&b_dpv[c]);
#pragma unroll 8
        for (int d = 0; d < 32; d++) {
            float vv = sV[tid][d];
#pragma unroll
            for (int c = 0; c < 16; c++) l[c] += vv * __ldg(&w_dpv[d * 16 + c]);
        }
        float m = l[0];
#pragma unroll
        for (int c = 1; c < 16; c++) m = fmaxf(m, l[c]);
        float s = 0.f;
#pragma unroll
        for (int c = 0; c < 16; c++) { l[c] = expf(l[c] - m); s += l[c]; }
        float inv = 1.f / s;
#pragma unroll
        for (int c = 0; c < 16; c++) sP[tid][c] = l[c] * inv;
    }
    __syncthreads();

    // phase 5: v_dp (all threads) + EMA(k_dp) scan (threads 32-63; sKdp synced)
#pragma unroll
    for (int r = 0; r < 4; r++) {
        int i = tid + (r << 7);
        int c = i >> 5, d = i & 31;
        float acc = 0.f;
#pragma unroll 8
        for (int e = 0; e < 64; e++) acc += sP[e][c] * sV[e][d];
        sVdp[c][d] = acc;
    }
    if (tid >= 32 && tid < 64) {
        const int d = tid - 32;
        float v = sKdp[0][d];
        sEK[0][d] = v;
#pragma unroll
        for (int g = 1; g < 16; g++) {
            v = om * v + al * sKdp[g][d];
            sEK[g][d] = v;
        }
    }
    __syncthreads();

    if (tid < 64) {
        const int e = tid;
        float st[16];
#pragma unroll
        for (int c = 0; c < 16; c++) {
            float acc = 0.f;
#pragma unroll
            for (int d = 0; d < 32; d++) acc += sEQ[e][d] * sEK[c][d];
            st[c] = acc * 5.656854249492381f;
        }
        float m = st[0];
#pragma unroll
        for (int c = 1; c < 16; c++) m = fmaxf(m, st[c]);
        float s = 0.f;
#pragma unroll
        for (int c = 0; c < 16; c++) { st[c] = expf(st[c] - m); s += st[c]; }
        float inv = 1.f / s;
#pragma unroll
        for (int c = 0; c < 16; c++) st[c] *= inv;
#pragma unroll
        for (int d = 0; d < 32; d++) {
            float acc = 0.f;
#pragma unroll
            for (int c = 0; c < 16; c++) acc += st[c] * sVdp[c][d];
            sEQ[e][d] = acc;
        }
    } else {
        const int idx = tid - 64;
        const int e = idx >> 1, h = idx & 1;
        float sh[16];
#pragma unroll
        for (int j = 0; j < 16; j++) {
            const int f = (h << 4) + j;
            float acc = 0.f;
#pragma unroll 8
            for (int a = 0; a < 64; a++) acc += sQ[a][e] * sK[a][f];
            sh[j] = acc * 8.0f;
        }
        float m = sh[0];
#pragma unroll
        for (int j = 1; j < 16; j++) m = fmaxf(m, sh[j]);
        m = fmaxf(m, __shfl_xor_sync(0xffffffffu, m, 1));
        float s = 0.f;
#pragma unroll
        for (int j = 0; j < 16; j++) { sh[j] = expf(sh[j] - m); s += sh[j]; }
        s += __shfl_xor_sync(0xffffffffu, s, 1);
        float inv = 1.f / s;
#pragma unroll
        for (int j = 0; j < 16; j++) sH[e][(h << 4) + j] = sh[j] * inv;
    }
    __syncthreads();

    uint32_t* otp = g_ot_hl + (size_t)u * 2048;
    uint32_t* ohp = g_oh_hl + (size_t)u * 2048;
#pragma unroll
    for (int r = 0; r < 16; r++) {
        int i = tid + (r << 7);
        int a = i >> 5, e = i & 31;
        otp[i] = packhl(sEQ[a][e]);
        float acc = 0.f;
#pragma unroll
        for (int f = 0; f < 32; f++) acc += sH[e][f] * sV[a][f];
        ohp[i] = packhl(acc);
    }
}

// ======================= BN statistics (deterministic two-stage) =======================
__global__ void __launch_bounds__(256) k_bn_partial(int slot)
{
    const int c = threadIdx.x;
    const size_t base = (size_t)blockIdx.x * 65536;
    float s = 0.f, q = 0.f;
    if (slot == 2) {
        for (int r = 0; r < 256; r++) {
            float v = g_pre[base + (size_t)(r << 8) + c];
            s += v; q += v * v;
        }
    } else {
        const uint32_t* x = slot ? g_oh_hl : g_ot_hl;
        for (int r = 0; r < 256; r++) {
            float v = unpackf(x[base + (size_t)(r << 8) + c]);
            s += v; q += v * v;
        }
    }
    g_psum[slot * 65536 + (blockIdx.x << 8) + c] = s;
    g_psq [slot * 65536 + (blockIdx.x << 8) + c] = q;
}

__global__ void __launch_bounds__(256) k_bn_finalize(
    int slot, const float* __restrict__ g, const float* __restrict__ b)
{
    const int c = threadIdx.x;
    const float* ps = g_psum + slot * 65536;
    const float* pq = g_psq  + slot * 65536;
    float s = 0.f, q = 0.f;
    for (int i = 0; i < 256; i++) { s += ps[(i << 8) + c]; q += pq[(i << 8) + c]; }
    const float inv = 1.f / 65536.f;
    float mean = s * inv;
    float var  = q * inv - mean * mean;
    float rstd = rsqrtf(var + 1e-5f);
    float sc = g[c] * rstd;
    g_S[slot * 256 + c] = sc;
    g_T[slot * 256 + c] = b[c] - mean * sc;
}

// ======================= Final BN apply =======================
__global__ void __launch_bounds__(256) k_bn_apply(float* __restrict__ out)
{
    const size_t i = (size_t)blockIdx.x * 256 + threadIdx.x;
    float4 v = ((const float4*)g_pre)[i];
    const int c = (int)((i & 63) << 2);
    const float* S = g_S + 512;
    const float* T = g_T + 512;
    v.x = v.x * S[c + 0] + T[c + 0];
    v.y = v.y * S[c + 1] + T[c + 1];
    v.z = v.z * S[c + 2] + T[c + 2];
    v.w = v.w * S[c + 3] + T[c + 3];
    ((float4*)out)[i] = v;
}

// ======================= launch =======================
extern "C" void kernel_launch(void* const* d_in, const int* in_sizes, int n_in,
                              void* d_out, int out_size)
{
    const float* src    = (const float*)d_in[0];
    const float* ema    = (const float*)d_in[1];
    const float* w_qkv  = (const float*)d_in[2];
    const float* b_qkv  = (const float*)d_in[3];
    const float* w_dpk  = (const float*)d_in[4];
    const float* b_dpk  = (const float*)d_in[5];
    const float* w_dpv  = (const float*)d_in[6];
    const float* b_dpv  = (const float*)d_in[7];
    const float* bn1_g  = (const float*)d_in[8];
    const float* bn1_b  = (const float*)d_in[9];
    const float* bn2_g  = (const float*)d_in[10];
    const float* bn2_b  = (const float*)d_in[11];
    const float* bna_g  = (const float*)d_in[12];
    const float* bna_b  = (const float*)d_in[13];
    const float* ff1_w1 = (const float*)d_in[14];
    const float* ff1_b1 = (const float*)d_in[15];
    const float* ff1_w2 = (const float*)d_in[16];
    const float* ff1_b2 = (const float*)d_in[17];
    const float* ff2_w1 = (const float*)d_in[18];
    const float* ff2_b1 = (const float*)d_in[19];
    const float* ff2_w2 = (const float*)d_in[20];
    const float* ff2_b2 = (const float*)d_in[21];
    float* out = (float*)d_out;

    // pre-split operands that don't depend on BN stats
    k_split_src<<<16384, 256>>>(src);
    k_prep_w<<<dim3(24,  8), dim3(32, 8)>>>(w_qkv,  WQ_O,  256, 768, -1);
    k_prep_w<<<dim3( 8, 16), dim3(32, 8)>>>(ff1_w2, W2A_O, 512, 256, -1);
    k_prep_w<<<dim3( 8, 16), dim3(32, 8)>>>(ff2_w2, W2B_O, 512, 256, -1);

    k_qkv_tc<<<dim3(N_QKV / 128, M_TOK / 128), 256>>>(b_qkv);
    k_attn<<<NUNITS, 128>>>(ema, w_dpk, b_dpk, w_dpv, b_dpv);
    k_bn_partial<<<256, 256>>>(0);
    k_bn_partial<<<256, 256>>>(1);
    k_bn_finalize<<<1, 256>>>(0, bn1_g, bn1_b);
    k_bn_finalize<<<1, 256>>>(1, bn2_g, bn2_b);

    // BN-folded ff1 weights + bias (need g_S/g_T from finalize)
    k_prep_w<<<dim3(16,  8), dim3(32, 8)>>>(ff1_w1, W1A_O, 256, 512, 0);
    k_prep_w<<<dim3(16,  8), dim3(32, 8)>>>(ff2_w1, W1B_O, 256, 512, 256);
    k_bias1<<<2, 512>>>(ff1_w1, ff1_b1, ff2_w1, ff2_b1);

    k_ff1_tc<<<dim3(D_FF / 128, M_TOK / 128, 2), 256>>>();
    k_g2_tc<<<dim3(C_DIM / 128, M_TOK / 128), 256>>>(ff1_b2, ff2_b2, src);
    k_bn_partial<<<256, 256>>>(2);
    k_bn_finalize<<<1, 256>>>(2, bna_g, bna_b);
    k_bn_apply<<<(M_TOK * C_DIM / 4) / 256, 256>>>(out);
}